// round 15
// baseline (speedup 1.0000x reference)
#include <cuda_runtime.h>

// DyDepthwiseConvAtten: B=1024, N=100, C=256, K=3  (rows = 102400)
// Round 15: exact R9 memory plan (2 rows/warp, coalesced 16B lane stride,
// 8 front-batched streaming LDG.128, invariants amortized 2x, 128-thread
// CTAs) with cheaper warp reductions:
//  - multi-value butterfly (coset pre-stages + group select) for the
//    3 weight dots per row (12 SHFL vs 15) and the 4 LN sums (15 vs 20)
//  - halo seam values fused into the neighbor shuffles (4 SHFL/row vs 6)
// 62 -> 47 MIO ops per warp; memory behavior identical to R9.

#define C_DIM 256
#define LN_EPS 1e-5f
#define WARPS_PER_CTA 4
#define RPW 2
#define FULL 0xffffffffu

// Reduce 3 values across the warp, broadcast all 3 to every lane.
__device__ __forceinline__ void reduce3(float p0, float p1, float p2, int lane,
                                        float& k0, float& k1, float& k2) {
    // pre-stages: each lane's p_i becomes sum over coset {l, l^8, l^16, l^24}
    p0 += __shfl_xor_sync(FULL, p0, 16);
    p1 += __shfl_xor_sync(FULL, p1, 16);
    p2 += __shfl_xor_sync(FULL, p2, 16);
    p0 += __shfl_xor_sync(FULL, p0, 8);
    p1 += __shfl_xor_sync(FULL, p1, 8);
    p2 += __shfl_xor_sync(FULL, p2, 8);
    // 8-lane group g reduces value g (groups 2,3 both carry p2; g3 redundant)
    const int grp = lane >> 3;
    float x = (grp == 0) ? p0 : (grp == 1) ? p1 : p2;
    x += __shfl_xor_sync(FULL, x, 4);
    x += __shfl_xor_sync(FULL, x, 2);
    x += __shfl_xor_sync(FULL, x, 1);
    k0 = __shfl_sync(FULL, x, 0);
    k1 = __shfl_sync(FULL, x, 8);
    k2 = __shfl_sync(FULL, x, 16);
}

// Reduce 4 values across the warp, broadcast all 4 to every lane.
__device__ __forceinline__ void reduce4(float a, float b, float c, float d, int lane,
                                        float& ra, float& rb, float& rc, float& rd) {
    a += __shfl_xor_sync(FULL, a, 16);
    b += __shfl_xor_sync(FULL, b, 16);
    c += __shfl_xor_sync(FULL, c, 16);
    d += __shfl_xor_sync(FULL, d, 16);
    a += __shfl_xor_sync(FULL, a, 8);
    b += __shfl_xor_sync(FULL, b, 8);
    c += __shfl_xor_sync(FULL, c, 8);
    d += __shfl_xor_sync(FULL, d, 8);
    const int grp = lane >> 3;
    float x = (grp == 0) ? a : (grp == 1) ? b : (grp == 2) ? c : d;
    x += __shfl_xor_sync(FULL, x, 4);
    x += __shfl_xor_sync(FULL, x, 2);
    x += __shfl_xor_sync(FULL, x, 1);
    ra = __shfl_sync(FULL, x, 0);
    rb = __shfl_sync(FULL, x, 8);
    rc = __shfl_sync(FULL, x, 16);
    rd = __shfl_sync(FULL, x, 24);
}

__global__ __launch_bounds__(WARPS_PER_CTA * 32)
void dydw_atten_kernel(const float* __restrict__ q,
                       const float* __restrict__ v,
                       const float* __restrict__ Ww,   // [3,256]
                       const float* __restrict__ bw,   // [3]
                       const float* __restrict__ gamma,
                       const float* __restrict__ beta,
                       float* __restrict__ out) {
    const int lane  = threadIdx.x & 31;
    const int wrp   = threadIdx.x >> 5;
    const int gwarp = blockIdx.x * WARPS_PER_CTA + wrp;

    const int    c0    = 4 * lane;          // chunk 0: channels [c0, c0+4)
    const int    c1    = 128 + 4 * lane;    // chunk 1: channels [c1, c1+4)
    const size_t baseA = (size_t)(gwarp * RPW)     * C_DIM;
    const size_t baseB = (size_t)(gwarp * RPW + 1) * C_DIM;

    // ---- front-batch ALL streaming loads for both rows (8x LDG.128) ----
    const float4 qa0 = __ldcs((const float4*)(q + baseA + c0));
    const float4 qa1 = __ldcs((const float4*)(q + baseA + c1));
    const float4 va0 = __ldcs((const float4*)(v + baseA + c0));
    const float4 va1 = __ldcs((const float4*)(v + baseA + c1));
    const float4 qb0 = __ldcs((const float4*)(q + baseB + c0));
    const float4 qb1 = __ldcs((const float4*)(q + baseB + c1));
    const float4 vb0 = __ldcs((const float4*)(v + baseB + c0));
    const float4 vb1 = __ldcs((const float4*)(v + baseB + c1));

    // ---- invariants: loaded ONCE per warp, amortized over 2 rows ----
    const float4 w00 = *(const float4*)(Ww + c0);
    const float4 w01 = *(const float4*)(Ww + c1);
    const float4 w10 = *(const float4*)(Ww + C_DIM + c0);
    const float4 w11 = *(const float4*)(Ww + C_DIM + c1);
    const float4 w20 = *(const float4*)(Ww + 2*C_DIM + c0);
    const float4 w21 = *(const float4*)(Ww + 2*C_DIM + c1);
    const float4 g0  = *(const float4*)(gamma + c0);
    const float4 g1  = *(const float4*)(gamma + c1);
    const float4 bt0 = *(const float4*)(beta  + c0);
    const float4 bt1 = *(const float4*)(beta  + c1);
    const float bw0 = bw[0], bw1 = bw[1], bw2 = bw[2];

    // ---- dynamic-weight dots, rows A and B; multi-value reductions ----
    float kwa0, kwa1, kwa2, kwb0, kwb1, kwb2;
    reduce3(qa0.x*w00.x + qa0.y*w00.y + qa0.z*w00.z + qa0.w*w00.w
          + qa1.x*w01.x + qa1.y*w01.y + qa1.z*w01.z + qa1.w*w01.w,
            qa0.x*w10.x + qa0.y*w10.y + qa0.z*w10.z + qa0.w*w10.w
          + qa1.x*w11.x + qa1.y*w11.y + qa1.z*w11.z + qa1.w*w11.w,
            qa0.x*w20.x + qa0.y*w20.y + qa0.z*w20.z + qa0.w*w20.w
          + qa1.x*w21.x + qa1.y*w21.y + qa1.z*w21.z + qa1.w*w21.w,
            lane, kwa0, kwa1, kwa2);
    reduce3(qb0.x*w00.x + qb0.y*w00.y + qb0.z*w00.z + qb0.w*w00.w
          + qb1.x*w01.x + qb1.y*w01.y + qb1.z*w01.z + qb1.w*w01.w,
            qb0.x*w10.x + qb0.y*w10.y + qb0.z*w10.z + qb0.w*w10.w
          + qb1.x*w11.x + qb1.y*w11.y + qb1.z*w11.z + qb1.w*w11.w,
            qb0.x*w20.x + qb0.y*w20.y + qb0.z*w20.z + qb0.w*w20.w
          + qb1.x*w21.x + qb1.y*w21.y + qb1.z*w21.z + qb1.w*w21.w,
            lane, kwb0, kwb1, kwb2);
    kwa0 += bw0; kwa1 += bw1; kwa2 += bw2;
    kwb0 += bw0; kwb1 += bw1; kwb2 += bw2;

    // ---- conv halos: seam values fused into the neighbor shuffles ----
    // right of chunk0: lane l<31 needs lane l+1's v0.x; lane 31 needs ch128
    // left  of chunk1: lane l>0  needs lane l-1's v1.w; lane 0  needs ch127
    const float tRa = (lane == 0)  ? va1.x : va0.x;
    const float tLa = (lane == 31) ? va0.w : va1.w;
    const float tRb = (lane == 0)  ? vb1.x : vb0.x;
    const float tLb = (lane == 31) ? vb0.w : vb1.w;
    const float ra0 = __shfl_sync(FULL, tRa, (lane + 1)  & 31);
    const float la1 = __shfl_sync(FULL, tLa, (lane + 31) & 31);
    const float rb0 = __shfl_sync(FULL, tRb, (lane + 1)  & 31);
    const float lb1 = __shfl_sync(FULL, tLb, (lane + 31) & 31);
    float la0 = __shfl_up_sync  (FULL, va0.w, 1);
    float ra1 = __shfl_down_sync(FULL, va1.x, 1);
    float lb0 = __shfl_up_sync  (FULL, vb0.w, 1);
    float rb1 = __shfl_down_sync(FULL, vb1.x, 1);
    if (lane == 0)  { la0 = 0.0f; lb0 = 0.0f; }   // v[-1] = 0
    if (lane == 31) { ra1 = 0.0f; rb1 = 0.0f; }   // v[256] = 0

    float oa[8], ob[8];
    {
        const float wA0[6] = { la0, va0.x, va0.y, va0.z, va0.w, ra0 };
        const float wA1[6] = { la1, va1.x, va1.y, va1.z, va1.w, ra1 };
        const float wB0[6] = { lb0, vb0.x, vb0.y, vb0.z, vb0.w, rb0 };
        const float wB1[6] = { lb1, vb1.x, vb1.y, vb1.z, vb1.w, rb1 };
        #pragma unroll
        for (int i = 0; i < 4; i++) {
            oa[i]     = wA0[i]*kwa0 + wA0[i+1]*kwa1 + wA0[i+2]*kwa2;
            oa[i + 4] = wA1[i]*kwa0 + wA1[i+1]*kwa1 + wA1[i+2]*kwa2;
            ob[i]     = wB0[i]*kwb0 + wB0[i+1]*kwb1 + wB0[i+2]*kwb2;
            ob[i + 4] = wB1[i]*kwb0 + wB1[i+1]*kwb1 + wB1[i+2]*kwb2;
        }
    }

    // ---- LayerNorm: 4 sums reduced jointly ----
    float sa1 = 0.0f, sa2 = 0.0f, sb1 = 0.0f, sb2 = 0.0f;
    #pragma unroll
    for (int i = 0; i < 8; i++) {
        sa1 += oa[i]; sa2 += oa[i]*oa[i];
        sb1 += ob[i]; sb2 += ob[i]*ob[i];
    }
    reduce4(sa1, sa2, sb1, sb2, lane, sa1, sa2, sb1, sb2);

    const float muA   = sa1 * (1.0f / C_DIM);
    const float rstdA = rsqrtf(sa2 * (1.0f / C_DIM) - muA*muA + LN_EPS);
    const float muB   = sb1 * (1.0f / C_DIM);
    const float rstdB = rsqrtf(sb2 * (1.0f / C_DIM) - muB*muB + LN_EPS);

    // ---- scale/shift + coalesced streaming stores ----
    float4 r;
    r.x = (oa[0]-muA)*rstdA*g0.x + bt0.x;
    r.y = (oa[1]-muA)*rstdA*g0.y + bt0.y;
    r.z = (oa[2]-muA)*rstdA*g0.z + bt0.z;
    r.w = (oa[3]-muA)*rstdA*g0.w + bt0.w;
    __stcs((float4*)(out + baseA + c0), r);
    r.x = (oa[4]-muA)*rstdA*g1.x + bt1.x;
    r.y = (oa[5]-muA)*rstdA*g1.y + bt1.y;
    r.z = (oa[6]-muA)*rstdA*g1.z + bt1.z;
    r.w = (oa[7]-muA)*rstdA*g1.w + bt1.w;
    __stcs((float4*)(out + baseA + c1), r);
    r.x = (ob[0]-muB)*rstdB*g0.x + bt0.x;
    r.y = (ob[1]-muB)*rstdB*g0.y + bt0.y;
    r.z = (ob[2]-muB)*rstdB*g0.z + bt0.z;
    r.w = (ob[3]-muB)*rstdB*g0.w + bt0.w;
    __stcs((float4*)(out + baseB + c0), r);
    r.x = (ob[4]-muB)*rstdB*g1.x + bt1.x;
    r.y = (ob[5]-muB)*rstdB*g1.y + bt1.y;
    r.z = (ob[6]-muB)*rstdB*g1.z + bt1.z;
    r.w = (ob[7]-muB)*rstdB*g1.w + bt1.w;
    __stcs((float4*)(out + baseB + c1), r);
}

extern "C" void kernel_launch(void* const* d_in, const int* in_sizes, int n_in,
                              void* d_out, int out_size) {
    const float* q     = (const float*)d_in[0];
    const float* v     = (const float*)d_in[1];
    const float* Ww    = (const float*)d_in[2];
    const float* bw    = (const float*)d_in[3];
    const float* gamma = (const float*)d_in[4];
    const float* beta  = (const float*)d_in[5];
    float* out = (float*)d_out;

    const int rows = out_size / C_DIM;                       // 102400
    const int ctas = rows / (RPW * WARPS_PER_CTA);           // 12800
    dydw_atten_kernel<<<ctas, WARPS_PER_CTA * 32>>>(q, v, Ww, bw, gamma, beta, out);
}

// round 16
// speedup vs baseline: 1.0413x; 1.0413x over previous
#include <cuda_runtime.h>

// DyDepthwiseConvAtten: B=1024, N=100, C=256, K=3  (rows = 102400)
// Round 16: R9 per-warp plan EXACTLY (2 rows/warp, coalesced 16B lane
// stride, 8 streaming LDG.128 front-batched, plain width-32 butterflies,
// invariants amortized 2x) -- with 256-thread CTAs (8 warps) so each CTA
// batches 16KB of contiguous streaming loads, and invariant (L2-hit) loads
// issued BEFORE the streaming batch so they don't queue behind DRAM misses
// in the L1tex wavefront FIFO.

#define C_DIM 256
#define LN_EPS 1e-5f
#define WARPS_PER_CTA 8
#define RPW 2
#define FULL 0xffffffffu

__global__ __launch_bounds__(WARPS_PER_CTA * 32)
void dydw_atten_kernel(const float* __restrict__ q,
                       const float* __restrict__ v,
                       const float* __restrict__ Ww,   // [3,256]
                       const float* __restrict__ bw,   // [3]
                       const float* __restrict__ gamma,
                       const float* __restrict__ beta,
                       float* __restrict__ out) {
    const int lane  = threadIdx.x & 31;
    const int wrp   = threadIdx.x >> 5;
    const int gwarp = blockIdx.x * WARPS_PER_CTA + wrp;

    const int    c0    = 4 * lane;          // chunk 0: channels [c0, c0+4)
    const int    c1    = 128 + 4 * lane;    // chunk 1: channels [c1, c1+4)
    const size_t baseA = (size_t)(gwarp * RPW)     * C_DIM;
    const size_t baseB = (size_t)(gwarp * RPW + 1) * C_DIM;

    // ---- invariants FIRST (L2-hit, short latency; ahead of DRAM misses) ----
    const float4 w00 = *(const float4*)(Ww + c0);
    const float4 w01 = *(const float4*)(Ww + c1);
    const float4 w10 = *(const float4*)(Ww + C_DIM + c0);
    const float4 w11 = *(const float4*)(Ww + C_DIM + c1);
    const float4 w20 = *(const float4*)(Ww + 2*C_DIM + c0);
    const float4 w21 = *(const float4*)(Ww + 2*C_DIM + c1);
    const float4 g0  = *(const float4*)(gamma + c0);
    const float4 g1  = *(const float4*)(gamma + c1);
    const float4 bt0 = *(const float4*)(beta  + c0);
    const float4 bt1 = *(const float4*)(beta  + c1);
    const float bw0 = bw[0], bw1 = bw[1], bw2 = bw[2];

    // ---- front-batch ALL streaming loads for both rows (8x LDG.128) ----
    const float4 qa0 = __ldcs((const float4*)(q + baseA + c0));
    const float4 qa1 = __ldcs((const float4*)(q + baseA + c1));
    const float4 qb0 = __ldcs((const float4*)(q + baseB + c0));
    const float4 qb1 = __ldcs((const float4*)(q + baseB + c1));
    const float4 va0 = __ldcs((const float4*)(v + baseA + c0));
    const float4 va1 = __ldcs((const float4*)(v + baseA + c1));
    const float4 vb0 = __ldcs((const float4*)(v + baseB + c0));
    const float4 vb1 = __ldcs((const float4*)(v + baseB + c1));

    // ---- dynamic-weight dots for BOTH rows; 6 independent butterfly chains ----
    float pa0 = qa0.x*w00.x + qa0.y*w00.y + qa0.z*w00.z + qa0.w*w00.w
              + qa1.x*w01.x + qa1.y*w01.y + qa1.z*w01.z + qa1.w*w01.w;
    float pa1 = qa0.x*w10.x + qa0.y*w10.y + qa0.z*w10.z + qa0.w*w10.w
              + qa1.x*w11.x + qa1.y*w11.y + qa1.z*w11.z + qa1.w*w11.w;
    float pa2 = qa0.x*w20.x + qa0.y*w20.y + qa0.z*w20.z + qa0.w*w20.w
              + qa1.x*w21.x + qa1.y*w21.y + qa1.z*w21.z + qa1.w*w21.w;
    float pb0 = qb0.x*w00.x + qb0.y*w00.y + qb0.z*w00.z + qb0.w*w00.w
              + qb1.x*w01.x + qb1.y*w01.y + qb1.z*w01.z + qb1.w*w01.w;
    float pb1 = qb0.x*w10.x + qb0.y*w10.y + qb0.z*w10.z + qb0.w*w10.w
              + qb1.x*w11.x + qb1.y*w11.y + qb1.z*w11.z + qb1.w*w11.w;
    float pb2 = qb0.x*w20.x + qb0.y*w20.y + qb0.z*w20.z + qb0.w*w20.w
              + qb1.x*w21.x + qb1.y*w21.y + qb1.z*w21.z + qb1.w*w21.w;
    #pragma unroll
    for (int off = 16; off > 0; off >>= 1) {
        pa0 += __shfl_xor_sync(FULL, pa0, off);
        pa1 += __shfl_xor_sync(FULL, pa1, off);
        pa2 += __shfl_xor_sync(FULL, pa2, off);
        pb0 += __shfl_xor_sync(FULL, pb0, off);
        pb1 += __shfl_xor_sync(FULL, pb1, off);
        pb2 += __shfl_xor_sync(FULL, pb2, off);
    }
    const float kwa0 = pa0 + bw0, kwa1 = pa1 + bw1, kwa2 = pa2 + bw2;
    const float kwb0 = pb0 + bw0, kwb1 = pb1 + bw1, kwb2 = pb2 + bw2;

    // ---- conv halos, both rows ----
    const float a127 = __shfl_sync(FULL, va0.w, 31);
    const float a128 = __shfl_sync(FULL, va1.x, 0);
    const float b127 = __shfl_sync(FULL, vb0.w, 31);
    const float b128 = __shfl_sync(FULL, vb1.x, 0);

    float la0 = __shfl_up_sync  (FULL, va0.w, 1);
    float ra0 = __shfl_down_sync(FULL, va0.x, 1);
    float la1 = __shfl_up_sync  (FULL, va1.w, 1);
    float ra1 = __shfl_down_sync(FULL, va1.x, 1);
    float lb0 = __shfl_up_sync  (FULL, vb0.w, 1);
    float rb0 = __shfl_down_sync(FULL, vb0.x, 1);
    float lb1 = __shfl_up_sync  (FULL, vb1.w, 1);
    float rb1 = __shfl_down_sync(FULL, vb1.x, 1);
    if (lane == 0)  { la0 = 0.0f; la1 = a127; lb0 = 0.0f; lb1 = b127; }
    if (lane == 31) { ra0 = a128; ra1 = 0.0f; rb0 = b128; rb1 = 0.0f; }

    float oa[8], ob[8];
    {
        const float wA0[6] = { la0, va0.x, va0.y, va0.z, va0.w, ra0 };
        const float wA1[6] = { la1, va1.x, va1.y, va1.z, va1.w, ra1 };
        const float wB0[6] = { lb0, vb0.x, vb0.y, vb0.z, vb0.w, rb0 };
        const float wB1[6] = { lb1, vb1.x, vb1.y, vb1.z, vb1.w, rb1 };
        #pragma unroll
        for (int i = 0; i < 4; i++) {
            oa[i]     = wA0[i]*kwa0 + wA0[i+1]*kwa1 + wA0[i+2]*kwa2;
            oa[i + 4] = wA1[i]*kwa0 + wA1[i+1]*kwa1 + wA1[i+2]*kwa2;
            ob[i]     = wB0[i]*kwb0 + wB0[i+1]*kwb1 + wB0[i+2]*kwb2;
            ob[i + 4] = wB1[i]*kwb0 + wB1[i+1]*kwb1 + wB1[i+2]*kwb2;
        }
    }

    // ---- LayerNorm: 4 independent butterfly chains ----
    float sa1 = 0.0f, sa2 = 0.0f, sb1 = 0.0f, sb2 = 0.0f;
    #pragma unroll
    for (int i = 0; i < 8; i++) {
        sa1 += oa[i]; sa2 += oa[i]*oa[i];
        sb1 += ob[i]; sb2 += ob[i]*ob[i];
    }
    #pragma unroll
    for (int off = 16; off > 0; off >>= 1) {
        sa1 += __shfl_xor_sync(FULL, sa1, off);
        sa2 += __shfl_xor_sync(FULL, sa2, off);
        sb1 += __shfl_xor_sync(FULL, sb1, off);
        sb2 += __shfl_xor_sync(FULL, sb2, off);
    }
    const float muA   = sa1 * (1.0f / C_DIM);
    const float rstdA = rsqrtf(sa2 * (1.0f / C_DIM) - muA*muA + LN_EPS);
    const float muB   = sb1 * (1.0f / C_DIM);
    const float rstdB = rsqrtf(sb2 * (1.0f / C_DIM) - muB*muB + LN_EPS);

    // ---- scale/shift + coalesced streaming stores ----
    float4 r;
    r.x = (oa[0]-muA)*rstdA*g0.x + bt0.x;
    r.y = (oa[1]-muA)*rstdA*g0.y + bt0.y;
    r.z = (oa[2]-muA)*rstdA*g0.z + bt0.z;
    r.w = (oa[3]-muA)*rstdA*g0.w + bt0.w;
    __stcs((float4*)(out + baseA + c0), r);
    r.x = (oa[4]-muA)*rstdA*g1.x + bt1.x;
    r.y = (oa[5]-muA)*rstdA*g1.y + bt1.y;
    r.z = (oa[6]-muA)*rstdA*g1.z + bt1.z;
    r.w = (oa[7]-muA)*rstdA*g1.w + bt1.w;
    __stcs((float4*)(out + baseA + c1), r);
    r.x = (ob[0]-muB)*rstdB*g0.x + bt0.x;
    r.y = (ob[1]-muB)*rstdB*g0.y + bt0.y;
    r.z = (ob[2]-muB)*rstdB*g0.z + bt0.z;
    r.w = (ob[3]-muB)*rstdB*g0.w + bt0.w;
    __stcs((float4*)(out + baseB + c0), r);
    r.x = (ob[4]-muB)*rstdB*g1.x + bt1.x;
    r.y = (ob[5]-muB)*rstdB*g1.y + bt1.y;
    r.z = (ob[6]-muB)*rstdB*g1.z + bt1.z;
    r.w = (ob[7]-muB)*rstdB*g1.w + bt1.w;
    __stcs((float4*)(out + baseB + c1), r);
}

extern "C" void kernel_launch(void* const* d_in, const int* in_sizes, int n_in,
                              void* d_out, int out_size) {
    const float* q     = (const float*)d_in[0];
    const float* v     = (const float*)d_in[1];
    const float* Ww    = (const float*)d_in[2];
    const float* bw    = (const float*)d_in[3];
    const float* gamma = (const float*)d_in[4];
    const float* beta  = (const float*)d_in[5];
    float* out = (float*)d_out;

    const int rows = out_size / C_DIM;                       // 102400
    const int ctas = rows / (RPW * WARPS_PER_CTA);           // 6400
    dydw_atten_kernel<<<ctas, WARPS_PER_CTA * 32>>>(q, v, Ww, bw, gamma, beta, out);
}